// round 15
// baseline (speedup 1.0000x reference)
#include <cuda_runtime.h>
#include <cuda_fp16.h>
#include <math.h>
#include <stdint.h>

#define D     768
#define SEQ   4096
#define BATCH 4
#define NTOK  (BATCH * SEQ)
#define SCALE 0.03608439182435161f  // 1/sqrt(768)

// ---------------------------------------------------------------------------
// Device-global scratch
// ---------------------------------------------------------------------------
__device__ __align__(256) __half g_Xf[NTOK * D];
__device__ __align__(256) __half g_Wf[3 * D * D];
__device__ __align__(256) __half g_Qf[NTOK * D];    // pre-scaled by SCALE
__device__ __align__(256) __half g_Kf[NTOK * D];
__device__ __align__(256) __half g_Vtf[NTOK * D];                 // [b][d][seq]
__device__ __align__(256) __half g_Ef[(size_t)BATCH * SEQ * SEQ]; // exp(S), fp16
__device__ float g_RS[(size_t)BATCH * 64 * SEQ];   // per-64col row partial sums

// fp16 core: 128x64 tiles, stride 72 (144B rows, conflict-free ldmatrix)
#define FSTR     72
#define TILE_F   (128 * FSTR * 2)        // 18432 B
#define STAGE_F  (2 * TILE_F)            // A|B = 36864
#define NSTAGE   3
#define DYN_F    (NSTAGE * STAGE_F)      // 110592 (2 CTAs/SM)

// ---------------------------------------------------------------------------
// PTX helpers
// ---------------------------------------------------------------------------
__device__ __forceinline__ uint32_t smem_u32(const void* p) {
    uint32_t a;
    asm("{ .reg .u64 t; cvta.to.shared.u64 t, %1; cvt.u32.u64 %0, t; }" : "=r"(a) : "l"(p));
    return a;
}
__device__ __forceinline__ void ldsm4(uint32_t r[4], uint32_t addr) {
    asm volatile("ldmatrix.sync.aligned.m8n8.x4.shared.b16 {%0,%1,%2,%3}, [%4];"
                 : "=r"(r[0]), "=r"(r[1]), "=r"(r[2]), "=r"(r[3]) : "r"(addr));
}
__device__ __forceinline__ void mma_f16(float c[4], const uint32_t a[4],
                                        uint32_t b0, uint32_t b1) {
    asm volatile(
        "mma.sync.aligned.m16n8k16.row.col.f32.f16.f16.f32 "
        "{%0,%1,%2,%3}, {%4,%5,%6,%7}, {%8,%9}, {%0,%1,%2,%3};"
        : "+f"(c[0]), "+f"(c[1]), "+f"(c[2]), "+f"(c[3])
        : "r"(a[0]), "r"(a[1]), "r"(a[2]), "r"(a[3]), "r"(b0), "r"(b1));
}
#define CP16(dst, src) asm volatile("cp.async.cg.shared.global [%0], [%1], 16;" :: "r"(dst), "l"(src) : "memory")
#define CP_COMMIT()    asm volatile("cp.async.commit_group;" ::: "memory")
#define CP_WAIT0()     asm volatile("cp.async.wait_group 0;" ::: "memory")
#define CP_WAIT1()     asm volatile("cp.async.wait_group 1;" ::: "memory")

__device__ __forceinline__ unsigned short hfu(__half x) {
    return *reinterpret_cast<unsigned short*>(&x);
}
__device__ __forceinline__ uint32_t pack_h2(float v0, float v1) {
    return (uint32_t)hfu(__float2half_rn(v0)) | ((uint32_t)hfu(__float2half_rn(v1)) << 16);
}

// ===========================================================================
// fp16 single-mma 128x128 GEMM core, 256 threads, K-chunk 64, 3-stage pipe.
// Warp-staggered kk/group order to de-phase L1 and tensor bursts across warps.
// ===========================================================================
__device__ __forceinline__ void load_chunk_f(
    uint32_t stage,
    const __half* __restrict__ A, int lda,
    const __half* __restrict__ B, int ldb, int k0)
{
    const int t   = threadIdx.x;
    const int seg = t & 7;        // 16B segment of a 128B row (64 f16)
    const int r0  = t >> 3;       // 0..31
    #pragma unroll
    for (int i = 0; i < 4; i++) {
        const int row = r0 + i * 32;
        const uint32_t so = (uint32_t)(row * FSTR + seg * 8) * 2;
        CP16(stage + so,          A + (size_t)row * lda + k0 + seg * 8);
        CP16(stage + TILE_F + so, B + (size_t)row * ldb + k0 + seg * 8);
    }
}

__device__ __forceinline__ void compute_chunk_f(
    uint32_t stage, const uint32_t offA[2], const uint32_t offB[4],
    int wrot, float acc[2][8][4])
{
    const uint32_t aT = stage, bT = stage + TILE_F;
    #pragma unroll
    for (int ki0 = 0; ki0 < 4; ki0++) {
        const int ki = (ki0 + wrot) & 3;          // per-warp kk order
        const uint32_t ko = (uint32_t)(ki * 16) * 2;
        uint32_t af[2][4];
        ldsm4(af[0], aT + offA[0] + ko);
        ldsm4(af[1], aT + offA[1] + ko);
        #pragma unroll
        for (int g0 = 0; g0 < 4; g0++) {
            const int g = (g0 + wrot) & 3;        // per-warp group order
            uint32_t bf[4];
            ldsm4(bf, bT + offB[g] + ko);
            #pragma unroll
            for (int mt = 0; mt < 2; mt++) {
                mma_f16(acc[mt][g * 2 + 0], af[mt], bf[0], bf[1]);
                mma_f16(acc[mt][g * 2 + 1], af[mt], bf[2], bf[3]);
            }
        }
    }
}

__device__ __forceinline__ void gemm_run_f(
    const __half* __restrict__ A, int lda,
    const __half* __restrict__ B, int ldb,
    int nchunks, float acc[2][8][4])
{
    extern __shared__ char dsm[];
    const uint32_t base = smem_u32(dsm);
    const int lane = threadIdx.x & 31;
    const int warp = threadIdx.x >> 5;
    const int wm = warp >> 1, wn = warp & 1;
    const int wrot = warp & 3;
    const int rowA = ((lane >> 3) & 1) * 8 + (lane & 7);
    const int colA = (lane >> 4) * 8;
    const int rowB = (lane >> 4) * 8 + (lane & 7);
    const int colB = ((lane >> 3) & 1) * 8;

    uint32_t offA[2], offB[4];
    #pragma unroll
    for (int mt = 0; mt < 2; mt++)
        offA[mt] = ((wm * 32 + mt * 16 + rowA) * FSTR + colA) * 2;
    #pragma unroll
    for (int g = 0; g < 4; g++)
        offB[g] = ((wn * 64 + g * 16 + rowB) * FSTR + colB) * 2;

    // Prologue: stages 0 and 1 in flight
    load_chunk_f(base, A, lda, B, ldb, 0);
    CP_COMMIT();
    if (nchunks > 1) {
        load_chunk_f(base + STAGE_F, A, lda, B, ldb, 64);
        CP_COMMIT();
    }

    int s = 0;
    for (int c = 0; c < nchunks; c++) {
        if (c + 1 < nchunks) CP_WAIT1(); else CP_WAIT0();
        __syncthreads();
        if (c + 2 < nchunks) {
            int s2 = s + 2; if (s2 >= NSTAGE) s2 -= NSTAGE;
            load_chunk_f(base + s2 * STAGE_F, A, lda, B, ldb, (c + 2) * 64);
            CP_COMMIT();
        }
        compute_chunk_f(base + s * STAGE_F, offA, offB, wrot, acc);
        if (++s == NSTAGE) s = 0;
    }
    __syncthreads();
}

// ===========================================================================
// Epilogues (128x128, 8-warp 2x2 layout)
// ===========================================================================
// pv epilogue: per-row scale by inv row-sum (from smem)
__device__ __forceinline__ void store_f32_rowscaled(
    float* __restrict__ C, size_t ldc, int row0, int col0,
    const float acc[2][8][4], const float* __restrict__ isum)
{
    const int lane = threadIdx.x & 31;
    const int warp = threadIdx.x >> 5;
    const int wm = warp >> 1, wn = warp & 1;
    #pragma unroll
    for (int mt = 0; mt < 2; mt++) {
        const int rt = wm * 32 + mt * 16 + (lane >> 2);
        const int r  = row0 + rt;
        const float i0 = isum[rt];
        const float i1 = isum[rt + 8];
        #pragma unroll
        for (int j = 0; j < 8; j++) {
            const int c = col0 + wn * 64 + j * 8 + (lane & 3) * 2;
            *(float2*)(C + (size_t)r * ldc + c) =
                make_float2(acc[mt][j][0] * i0, acc[mt][j][1] * i0);
            *(float2*)(C + (size_t)(r + 8) * ldc + c) =
                make_float2(acc[mt][j][2] * i1, acc[mt][j][3] * i1);
        }
    }
}

__device__ __forceinline__ void store_f16_t(
    __half* __restrict__ Cf, size_t ldc, int row0, int col0,
    const float acc[2][8][4], float scale)
{
    const int lane = threadIdx.x & 31;
    const int warp = threadIdx.x >> 5;
    const int wm = warp >> 1, wn = warp & 1;
    #pragma unroll
    for (int mt = 0; mt < 2; mt++) {
        const int r = row0 + wm * 32 + mt * 16 + (lane >> 2);
        #pragma unroll
        for (int j = 0; j < 8; j++) {
            const int c = col0 + wn * 64 + j * 8 + (lane & 3) * 2;
            *(uint32_t*)(Cf + (size_t)r * ldc + c) =
                pack_h2(acc[mt][j][0] * scale, acc[mt][j][1] * scale);
            *(uint32_t*)(Cf + (size_t)(r + 8) * ldc + c) =
                pack_h2(acc[mt][j][2] * scale, acc[mt][j][3] * scale);
        }
    }
}

// scores epilogue: E = exp(S) (fp16), causal mask on diagonal tiles, and
// deterministic per-row partial sums (64-col granularity) into g_RS.
__device__ __forceinline__ void store_exp_t(
    __half* __restrict__ Ef, int row0, int col0,
    const float acc[2][8][4], bool diag, int b, int bx)
{
    const int lane = threadIdx.x & 31;
    const int warp = threadIdx.x >> 5;
    const int wm = warp >> 1, wn = warp & 1;
    float* rs_base = g_RS + ((size_t)(b * 64 + bx * 2 + wn)) * SEQ + row0;

    #pragma unroll
    for (int mt = 0; mt < 2; mt++) {
        const int rt = wm * 32 + mt * 16 + (lane >> 2);   // tile-local row
        float rs0 = 0.0f, rs1 = 0.0f;
        #pragma unroll
        for (int j = 0; j < 8; j++) {
            const int ct = wn * 64 + j * 8 + (lane & 3) * 2;  // tile-local col
            float e0 = (!diag || ct     <= rt)     ? __expf(acc[mt][j][0]) : 0.0f;
            float e1 = (!diag || ct + 1 <= rt)     ? __expf(acc[mt][j][1]) : 0.0f;
            float e2 = (!diag || ct     <= rt + 8) ? __expf(acc[mt][j][2]) : 0.0f;
            float e3 = (!diag || ct + 1 <= rt + 8) ? __expf(acc[mt][j][3]) : 0.0f;
            *(uint32_t*)(Ef + (size_t)(row0 + rt) * SEQ + col0 + ct)     = pack_h2(e0, e1);
            *(uint32_t*)(Ef + (size_t)(row0 + rt + 8) * SEQ + col0 + ct) = pack_h2(e2, e3);
            rs0 += e0 + e1;
            rs1 += e2 + e3;
        }
        rs0 += __shfl_xor_sync(0xFFFFFFFF, rs0, 1);
        rs0 += __shfl_xor_sync(0xFFFFFFFF, rs0, 2);
        rs1 += __shfl_xor_sync(0xFFFFFFFF, rs1, 1);
        rs1 += __shfl_xor_sync(0xFFFFFFFF, rs1, 2);
        if ((lane & 3) == 0) {
            rs_base[rt]     = rs0;
            rs_base[rt + 8] = rs1;
        }
    }
}

// Transposed fp16 V store via smem (128x128 tile)
#define VT_STRIDE 136
__device__ __forceinline__ void store_vt_f16(int row0, int col0, const float acc[2][8][4])
{
    extern __shared__ char dsm[];
    unsigned short* sp = (unsigned short*)dsm;
    const int tid  = threadIdx.x;
    const int lane = tid & 31;
    const int warp = tid >> 5;
    const int wm = warp >> 1, wn = warp & 1;

    #pragma unroll
    for (int mt = 0; mt < 2; mt++) {
        const int r = wm * 32 + mt * 16 + (lane >> 2);
        #pragma unroll
        for (int j = 0; j < 8; j++) {
            const int c = wn * 64 + j * 8 + (lane & 3) * 2;
            #pragma unroll
            for (int e = 0; e < 4; e++)
                sp[(r + (e >> 1) * 8) * VT_STRIDE + c + (e & 1)] =
                    hfu(__float2half_rn(acc[mt][j][e]));
        }
    }
    __syncthreads();

    const int b   = row0 >> 12;
    const int rin = row0 & (SEQ - 1);
    const int d   = tid >> 1;
    const int ks  = (tid & 1) * 64;
    __half* dst = g_Vtf + (size_t)b * D * SEQ + (size_t)(col0 + d) * SEQ + rin + ks;
    #pragma unroll
    for (int g = 0; g < 8; g++) {
        uint32_t w[4];
        #pragma unroll
        for (int h = 0; h < 4; h++) {
            uint32_t a0 = sp[(ks + g * 8 + h * 2) * VT_STRIDE + d];
            uint32_t a1 = sp[(ks + g * 8 + h * 2 + 1) * VT_STRIDE + d];
            w[h] = a0 | (a1 << 16);
        }
        *(uint4*)(dst + g * 8) = make_uint4(w[0], w[1], w[2], w[3]);
    }
}

// ===========================================================================
// Kernels
// ===========================================================================
__global__ void __launch_bounds__(256) cvt_kernel(const float* __restrict__ src,
                                                  __half* __restrict__ dst, int n)
{
    int i = (blockIdx.x * 256 + threadIdx.x) * 8;
    if (i >= n) return;
    float4 v0 = *(const float4*)(src + i);
    float4 v1 = *(const float4*)(src + i + 4);
    *(uint4*)(dst + i) = make_uint4(pack_h2(v0.x, v0.y), pack_h2(v0.z, v0.w),
                                    pack_h2(v1.x, v1.y), pack_h2(v1.z, v1.w));
}

// All three weight matrices in one launch (z selects Wq/Wk/Wv)
__global__ void __launch_bounds__(256) cvtw_kernel(const float* __restrict__ wq,
                                                   const float* __restrict__ wk,
                                                   const float* __restrict__ wv)
{
    const float* src = (blockIdx.z == 0) ? wq : (blockIdx.z == 1) ? wk : wv;
    __half* dst = g_Wf + (size_t)blockIdx.z * D * D;
    int i = (blockIdx.x * 256 + threadIdx.x) * 8;
    float4 v0 = *(const float4*)(src + i);
    float4 v1 = *(const float4*)(src + i + 4);
    *(uint4*)(dst + i) = make_uint4(pack_h2(v0.x, v0.y), pack_h2(v0.z, v0.w),
                                    pack_h2(v1.x, v1.y), pack_h2(v1.z, v1.w));
}

// Q (z=0, pre-scaled), K (z=1), V transposed (z=2)
__global__ void __launch_bounds__(256, 2) qkv_mm()
{
    const int z    = blockIdx.z;
    const int row0 = blockIdx.y * 128;
    const int col0 = blockIdx.x * 128;

    float acc[2][8][4] = {};
    gemm_run_f(g_Xf + (size_t)row0 * D, D,
               g_Wf + (size_t)z * D * D + (size_t)col0 * D, D, D / 64, acc);

    if (z == 0)      store_f16_t(g_Qf, D, row0, col0, acc, SCALE);
    else if (z == 1) store_f16_t(g_Kf, D, row0, col0, acc, 1.0f);
    else             store_vt_f16(row0, col0, acc);
}

// S tile -> exp -> fp16 E + row partial sums
__global__ void __launch_bounds__(256, 2) scores_mm()
{
    const int t = blockIdx.x;
    int by = (int)((sqrtf(8.0f * t + 1.0f) - 1.0f) * 0.5f);
    while ((by + 1) * (by + 2) / 2 <= t) by++;
    while (by * (by + 1) / 2 > t) by--;
    const int bx = t - by * (by + 1) / 2;
    const int b  = blockIdx.y;
    const int row0 = by * 128, col0 = bx * 128;
    const size_t qoff = (size_t)b * SEQ * D;

    float acc[2][8][4] = {};
    gemm_run_f(g_Qf + qoff + (size_t)row0 * D, D,
               g_Kf + qoff + (size_t)col0 * D, D, D / 64, acc);
    store_exp_t(g_Ef + (size_t)b * SEQ * SEQ, row0, col0, acc, by == bx, b, bx);
}

// PV with rowsum folded into the epilogue (deterministic fixed-order sums)
__global__ void __launch_bounds__(256, 2) pv_mm(float* __restrict__ Out)
{
    extern __shared__ char dsm[];
    const int b    = blockIdx.z;
    const int by   = (gridDim.y - 1) - blockIdx.y;   // heavy rows first
    const int row0 = by * 128;
    const int col0 = blockIdx.x * 128;
    const int nchunks = (by + 1) * 2;                // Klim / 64

    const size_t poff = (size_t)b * SEQ * SEQ + (size_t)row0 * SEQ;
    const size_t voff = (size_t)b * D * SEQ + (size_t)col0 * SEQ;

    float acc[2][8][4] = {};
    gemm_run_f(g_Ef + poff, SEQ, g_Vtf + voff, SEQ, nchunks, acc);

    // inline rowsum: thread t<128 handles row row0+t (fixed order, deterministic)
    float* s_inv = (float*)dsm;      // gemm_run_f ended with __syncthreads()
    if (threadIdx.x < 128) {
        const float* rs = g_RS + ((size_t)b * 64) * SEQ + row0 + threadIdx.x;
        float s = 0.0f;
        for (int i = 0; i < nchunks; i++) s += rs[(size_t)i * SEQ];
        s_inv[threadIdx.x] = 1.0f / s;
    }
    __syncthreads();

    store_f32_rowscaled(Out + (size_t)b * SEQ * D, D, row0, col0, acc, s_inv);
}

// ---------------------------------------------------------------------------
extern "C" void kernel_launch(void* const* d_in, const int* in_sizes, int n_in,
                              void* d_out, int out_size)
{
    const float* X  = (const float*)d_in[0];
    const float* Wq = (const float*)d_in[1];
    const float* Wk = (const float*)d_in[2];
    const float* Wv = (const float*)d_in[3];
    float* Out = (float*)d_out;

    static bool init_done = false;
    if (!init_done) {
        cudaFuncSetAttribute(qkv_mm,    cudaFuncAttributeMaxDynamicSharedMemorySize, DYN_F);
        cudaFuncSetAttribute(scores_mm, cudaFuncAttributeMaxDynamicSharedMemorySize, DYN_F);
        cudaFuncSetAttribute(pv_mm,     cudaFuncAttributeMaxDynamicSharedMemorySize, DYN_F);
        init_done = true;
    }

    __half* xf;
    cudaGetSymbolAddress((void**)&xf, g_Xf);

    cvt_kernel<<<(NTOK * D) / 2048, 256>>>(X, xf, NTOK * D);
    cvtw_kernel<<<dim3((D * D) / 2048, 1, 3), 256>>>(Wq, Wk, Wv);

    qkv_mm<<<dim3(D / 128, NTOK / 128, 3), 256, DYN_F>>>();
    scores_mm<<<dim3(528, BATCH), 256, DYN_F>>>();
    pv_mm<<<dim3(D / 128, SEQ / 128, BATCH), 256, DYN_F>>>(Out);
}

// round 16
// speedup vs baseline: 6.9281x; 6.9281x over previous
#include <cuda_runtime.h>
#include <cuda_fp16.h>
#include <math.h>
#include <stdint.h>

#define D     768
#define SEQ   4096
#define BATCH 4
#define NTOK  (BATCH * SEQ)
#define SCALE 0.03608439182435161f  // 1/sqrt(768)

// ---------------------------------------------------------------------------
// Device-global scratch
// ---------------------------------------------------------------------------
__device__ __align__(256) __half g_Xf[NTOK * D];
__device__ __align__(256) __half g_Wf[3 * D * D];
__device__ __align__(256) __half g_Qf[NTOK * D];    // pre-scaled by SCALE
__device__ __align__(256) __half g_Kf[NTOK * D];
__device__ __align__(256) __half g_Vtf[NTOK * D];                 // [b][d][seq]
__device__ __align__(256) __half g_Ef[(size_t)BATCH * SEQ * SEQ]; // exp(S), fp16
__device__ float g_RS[(size_t)BATCH * 64 * SEQ];   // per-64col row partial sums

// fp16 core: 128x64 tiles, stride 72 (144B rows, conflict-free ldmatrix)
#define FSTR     72
#define TILE_F   (128 * FSTR * 2)        // 18432 B
#define STAGE_F  (2 * TILE_F)            // A|B = 36864
#define NSTAGE   3
#define DYN_F    (NSTAGE * STAGE_F)      // 110592 (2 CTAs/SM)

// ---------------------------------------------------------------------------
// PTX helpers
// ---------------------------------------------------------------------------
__device__ __forceinline__ uint32_t smem_u32(const void* p) {
    uint32_t a;
    asm("{ .reg .u64 t; cvta.to.shared.u64 t, %1; cvt.u32.u64 %0, t; }" : "=r"(a) : "l"(p));
    return a;
}
__device__ __forceinline__ void ldsm4(uint32_t r[4], uint32_t addr) {
    asm volatile("ldmatrix.sync.aligned.m8n8.x4.shared.b16 {%0,%1,%2,%3}, [%4];"
                 : "=r"(r[0]), "=r"(r[1]), "=r"(r[2]), "=r"(r[3]) : "r"(addr));
}
__device__ __forceinline__ void mma_f16(float c[4], const uint32_t a[4],
                                        uint32_t b0, uint32_t b1) {
    asm volatile(
        "mma.sync.aligned.m16n8k16.row.col.f32.f16.f16.f32 "
        "{%0,%1,%2,%3}, {%4,%5,%6,%7}, {%8,%9}, {%0,%1,%2,%3};"
        : "+f"(c[0]), "+f"(c[1]), "+f"(c[2]), "+f"(c[3])
        : "r"(a[0]), "r"(a[1]), "r"(a[2]), "r"(a[3]), "r"(b0), "r"(b1));
}
#define CP16(dst, src) asm volatile("cp.async.cg.shared.global [%0], [%1], 16;" :: "r"(dst), "l"(src) : "memory")
#define CP_COMMIT()    asm volatile("cp.async.commit_group;" ::: "memory")
#define CP_WAIT0()     asm volatile("cp.async.wait_group 0;" ::: "memory")
#define CP_WAIT1()     asm volatile("cp.async.wait_group 1;" ::: "memory")

__device__ __forceinline__ unsigned short hfu(__half x) {
    return *reinterpret_cast<unsigned short*>(&x);
}
__device__ __forceinline__ uint32_t pack_h2(float v0, float v1) {
    return (uint32_t)hfu(__float2half_rn(v0)) | ((uint32_t)hfu(__float2half_rn(v1)) << 16);
}

// ===========================================================================
// fp16 single-mma 128x128 GEMM core, 256 threads, K-chunk 64, 3-stage pipe
// (exact R11 structure — all indices compile-time constant)
// ===========================================================================
__device__ __forceinline__ void load_chunk_f(
    uint32_t stage,
    const __half* __restrict__ A, int lda,
    const __half* __restrict__ B, int ldb, int k0)
{
    const int t   = threadIdx.x;
    const int seg = t & 7;        // 16B segment of a 128B row (64 f16)
    const int r0  = t >> 3;       // 0..31
    #pragma unroll
    for (int i = 0; i < 4; i++) {
        const int row = r0 + i * 32;
        const uint32_t so = (uint32_t)(row * FSTR + seg * 8) * 2;
        CP16(stage + so,          A + (size_t)row * lda + k0 + seg * 8);
        CP16(stage + TILE_F + so, B + (size_t)row * ldb + k0 + seg * 8);
    }
}

__device__ __forceinline__ void compute_chunk_f(
    uint32_t stage, const uint32_t offA[2], const uint32_t offB[4],
    float acc[2][8][4])
{
    const uint32_t aT = stage, bT = stage + TILE_F;
    #pragma unroll
    for (int kk = 0; kk < 64; kk += 16) {
        uint32_t af[2][4];
        ldsm4(af[0], aT + offA[0] + kk * 2);
        ldsm4(af[1], aT + offA[1] + kk * 2);
        #pragma unroll
        for (int g = 0; g < 4; g++) {
            uint32_t bf[4];
            ldsm4(bf, bT + offB[g] + kk * 2);
            #pragma unroll
            for (int mt = 0; mt < 2; mt++) {
                #pragma unroll
                for (int nt = 0; nt < 2; nt++)
                    mma_f16(acc[mt][g * 2 + nt], af[mt], bf[nt * 2], bf[nt * 2 + 1]);
            }
        }
    }
}

__device__ __forceinline__ void gemm_run_f(
    const __half* __restrict__ A, int lda,
    const __half* __restrict__ B, int ldb,
    int nchunks, float acc[2][8][4])
{
    extern __shared__ char dsm[];
    const uint32_t base = smem_u32(dsm);
    const int lane = threadIdx.x & 31;
    const int warp = threadIdx.x >> 5;
    const int wm = warp >> 1, wn = warp & 1;
    const int rowA = ((lane >> 3) & 1) * 8 + (lane & 7);
    const int colA = (lane >> 4) * 8;
    const int rowB = (lane >> 4) * 8 + (lane & 7);
    const int colB = ((lane >> 3) & 1) * 8;

    uint32_t offA[2], offB[4];
    #pragma unroll
    for (int mt = 0; mt < 2; mt++)
        offA[mt] = ((wm * 32 + mt * 16 + rowA) * FSTR + colA) * 2;
    #pragma unroll
    for (int g = 0; g < 4; g++)
        offB[g] = ((wn * 64 + g * 16 + rowB) * FSTR + colB) * 2;

    // Prologue: stages 0 and 1 in flight
    load_chunk_f(base, A, lda, B, ldb, 0);
    CP_COMMIT();
    if (nchunks > 1) {
        load_chunk_f(base + STAGE_F, A, lda, B, ldb, 64);
        CP_COMMIT();
    }

    int s = 0;
    for (int c = 0; c < nchunks; c++) {
        if (c + 1 < nchunks) CP_WAIT1(); else CP_WAIT0();
        __syncthreads();
        if (c + 2 < nchunks) {
            int s2 = s + 2; if (s2 >= NSTAGE) s2 -= NSTAGE;
            load_chunk_f(base + s2 * STAGE_F, A, lda, B, ldb, (c + 2) * 64);
            CP_COMMIT();
        }
        compute_chunk_f(base + s * STAGE_F, offA, offB, acc);
        if (++s == NSTAGE) s = 0;
    }
    __syncthreads();
}

// ===========================================================================
// Epilogues (128x128, 8-warp 2x2 layout)
// ===========================================================================
__device__ __forceinline__ void store_f32_rowscaled(
    float* __restrict__ C, size_t ldc, int row0, int col0,
    const float acc[2][8][4], const float* __restrict__ isum)
{
    const int lane = threadIdx.x & 31;
    const int warp = threadIdx.x >> 5;
    const int wm = warp >> 1, wn = warp & 1;
    #pragma unroll
    for (int mt = 0; mt < 2; mt++) {
        const int rt = wm * 32 + mt * 16 + (lane >> 2);
        const int r  = row0 + rt;
        const float i0 = isum[rt];
        const float i1 = isum[rt + 8];
        #pragma unroll
        for (int j = 0; j < 8; j++) {
            const int c = col0 + wn * 64 + j * 8 + (lane & 3) * 2;
            *(float2*)(C + (size_t)r * ldc + c) =
                make_float2(acc[mt][j][0] * i0, acc[mt][j][1] * i0);
            *(float2*)(C + (size_t)(r + 8) * ldc + c) =
                make_float2(acc[mt][j][2] * i1, acc[mt][j][3] * i1);
        }
    }
}

__device__ __forceinline__ void store_f16_t(
    __half* __restrict__ Cf, size_t ldc, int row0, int col0,
    const float acc[2][8][4], float scale)
{
    const int lane = threadIdx.x & 31;
    const int warp = threadIdx.x >> 5;
    const int wm = warp >> 1, wn = warp & 1;
    #pragma unroll
    for (int mt = 0; mt < 2; mt++) {
        const int r = row0 + wm * 32 + mt * 16 + (lane >> 2);
        #pragma unroll
        for (int j = 0; j < 8; j++) {
            const int c = col0 + wn * 64 + j * 8 + (lane & 3) * 2;
            *(uint32_t*)(Cf + (size_t)r * ldc + c) =
                pack_h2(acc[mt][j][0] * scale, acc[mt][j][1] * scale);
            *(uint32_t*)(Cf + (size_t)(r + 8) * ldc + c) =
                pack_h2(acc[mt][j][2] * scale, acc[mt][j][3] * scale);
        }
    }
}

// scores epilogue: E = exp(S) (fp16), causal mask on diagonal tiles, and
// deterministic per-row partial sums (64-col granularity) into g_RS.
__device__ __forceinline__ void store_exp_t(
    __half* __restrict__ Ef, int row0, int col0,
    const float acc[2][8][4], bool diag, int b, int bx)
{
    const int lane = threadIdx.x & 31;
    const int warp = threadIdx.x >> 5;
    const int wm = warp >> 1, wn = warp & 1;
    float* rs_base = g_RS + ((size_t)(b * 64 + bx * 2 + wn)) * SEQ + row0;

    #pragma unroll
    for (int mt = 0; mt < 2; mt++) {
        const int rt = wm * 32 + mt * 16 + (lane >> 2);   // tile-local row
        float rs0 = 0.0f, rs1 = 0.0f;
        #pragma unroll
        for (int j = 0; j < 8; j++) {
            const int ct = wn * 64 + j * 8 + (lane & 3) * 2;  // tile-local col
            float e0 = (!diag || ct     <= rt)     ? __expf(acc[mt][j][0]) : 0.0f;
            float e1 = (!diag || ct + 1 <= rt)     ? __expf(acc[mt][j][1]) : 0.0f;
            float e2 = (!diag || ct     <= rt + 8) ? __expf(acc[mt][j][2]) : 0.0f;
            float e3 = (!diag || ct + 1 <= rt + 8) ? __expf(acc[mt][j][3]) : 0.0f;
            *(uint32_t*)(Ef + (size_t)(row0 + rt) * SEQ + col0 + ct)     = pack_h2(e0, e1);
            *(uint32_t*)(Ef + (size_t)(row0 + rt + 8) * SEQ + col0 + ct) = pack_h2(e2, e3);
            rs0 += e0 + e1;
            rs1 += e2 + e3;
        }
        rs0 += __shfl_xor_sync(0xFFFFFFFF, rs0, 1);
        rs0 += __shfl_xor_sync(0xFFFFFFFF, rs0, 2);
        rs1 += __shfl_xor_sync(0xFFFFFFFF, rs1, 1);
        rs1 += __shfl_xor_sync(0xFFFFFFFF, rs1, 2);
        if ((lane & 3) == 0) {
            rs_base[rt]     = rs0;
            rs_base[rt + 8] = rs1;
        }
    }
}

// Transposed fp16 V store via smem (128x128 tile)
#define VT_STRIDE 136
__device__ __forceinline__ void store_vt_f16(int row0, int col0, const float acc[2][8][4])
{
    extern __shared__ char dsm[];
    unsigned short* sp = (unsigned short*)dsm;
    const int tid  = threadIdx.x;
    const int lane = tid & 31;
    const int warp = tid >> 5;
    const int wm = warp >> 1, wn = warp & 1;

    #pragma unroll
    for (int mt = 0; mt < 2; mt++) {
        const int r = wm * 32 + mt * 16 + (lane >> 2);
        #pragma unroll
        for (int j = 0; j < 8; j++) {
            const int c = wn * 64 + j * 8 + (lane & 3) * 2;
            #pragma unroll
            for (int e = 0; e < 4; e++)
                sp[(r + (e >> 1) * 8) * VT_STRIDE + c + (e & 1)] =
                    hfu(__float2half_rn(acc[mt][j][e]));
        }
    }
    __syncthreads();

    const int b   = row0 >> 12;
    const int rin = row0 & (SEQ - 1);
    const int d   = tid >> 1;
    const int ks  = (tid & 1) * 64;
    __half* dst = g_Vtf + (size_t)b * D * SEQ + (size_t)(col0 + d) * SEQ + rin + ks;
    #pragma unroll
    for (int g = 0; g < 8; g++) {
        uint32_t w[4];
        #pragma unroll
        for (int h = 0; h < 4; h++) {
            uint32_t a0 = sp[(ks + g * 8 + h * 2) * VT_STRIDE + d];
            uint32_t a1 = sp[(ks + g * 8 + h * 2 + 1) * VT_STRIDE + d];
            w[h] = a0 | (a1 << 16);
        }
        *(uint4*)(dst + g * 8) = make_uint4(w[0], w[1], w[2], w[3]);
    }
}

// ===========================================================================
// Kernels
// ===========================================================================
__global__ void __launch_bounds__(256) cvt_kernel(const float* __restrict__ src,
                                                  __half* __restrict__ dst, int n)
{
    int i = (blockIdx.x * 256 + threadIdx.x) * 8;
    if (i >= n) return;
    float4 v0 = *(const float4*)(src + i);
    float4 v1 = *(const float4*)(src + i + 4);
    *(uint4*)(dst + i) = make_uint4(pack_h2(v0.x, v0.y), pack_h2(v0.z, v0.w),
                                    pack_h2(v1.x, v1.y), pack_h2(v1.z, v1.w));
}

// All three weight matrices in one launch (z selects Wq/Wk/Wv)
__global__ void __launch_bounds__(256) cvtw_kernel(const float* __restrict__ wq,
                                                   const float* __restrict__ wk,
                                                   const float* __restrict__ wv)
{
    const float* src = (blockIdx.z == 0) ? wq : (blockIdx.z == 1) ? wk : wv;
    __half* dst = g_Wf + (size_t)blockIdx.z * D * D;
    int i = (blockIdx.x * 256 + threadIdx.x) * 8;
    float4 v0 = *(const float4*)(src + i);
    float4 v1 = *(const float4*)(src + i + 4);
    *(uint4*)(dst + i) = make_uint4(pack_h2(v0.x, v0.y), pack_h2(v0.z, v0.w),
                                    pack_h2(v1.x, v1.y), pack_h2(v1.z, v1.w));
}

// Q (z=0, pre-scaled), K (z=1), V transposed (z=2)
__global__ void __launch_bounds__(256, 2) qkv_mm()
{
    const int z    = blockIdx.z;
    const int row0 = blockIdx.y * 128;
    const int col0 = blockIdx.x * 128;

    float acc[2][8][4] = {};
    gemm_run_f(g_Xf + (size_t)row0 * D, D,
               g_Wf + (size_t)z * D * D + (size_t)col0 * D, D, D / 64, acc);

    if (z == 0)      store_f16_t(g_Qf, D, row0, col0, acc, SCALE);
    else if (z == 1) store_f16_t(g_Kf, D, row0, col0, acc, 1.0f);
    else             store_vt_f16(row0, col0, acc);
}

// S tile -> exp -> fp16 E + row partial sums
__global__ void __launch_bounds__(256, 2) scores_mm()
{
    const int t = blockIdx.x;
    int by = (int)((sqrtf(8.0f * t + 1.0f) - 1.0f) * 0.5f);
    while ((by + 1) * (by + 2) / 2 <= t) by++;
    while (by * (by + 1) / 2 > t) by--;
    const int bx = t - by * (by + 1) / 2;
    const int b  = blockIdx.y;
    const int row0 = by * 128, col0 = bx * 128;
    const size_t qoff = (size_t)b * SEQ * D;

    float acc[2][8][4] = {};
    gemm_run_f(g_Qf + qoff + (size_t)row0 * D, D,
               g_Kf + qoff + (size_t)col0 * D, D, D / 64, acc);
    store_exp_t(g_Ef + (size_t)b * SEQ * SEQ, row0, col0, acc, by == bx, b, bx);
}

// PV: cross-batch heavy-first scheduling, rowsum hoisted before mainloop.
// blockIdx.y encodes (row_rank, batch): heavy row-tiles of ALL batches first.
__global__ void __launch_bounds__(256, 2) pv_mm(float* __restrict__ Out)
{
    extern __shared__ char dsm[];
    const int idx  = blockIdx.y;
    const int b    = idx & 3;
    const int by   = (SEQ / 128 - 1) - (idx >> 2);   // heavy rows first, all batches
    const int row0 = by * 128;
    const int col0 = blockIdx.x * 128;
    const int nchunks = (by + 1) * 2;                // Klim / 64

    // rowsum first: depends only on scores_mm (done); loads overlap GEMM prologue
    float* s_inv = (float*)(dsm + DYN_F - 512);      // last 512B of dyn smem,
    if (threadIdx.x < 128) {                         // untouched until epilogue? no:
        const float* rs = g_RS + ((size_t)b * 64) * SEQ + row0 + threadIdx.x;
        float s = 0.0f;
        for (int i = 0; i < nchunks; i++) s += rs[(size_t)i * SEQ];
        s_inv[threadIdx.x] = 1.0f / s;               // NOTE: stage area overlap below
    }
    // s_inv lives in registers via reload after mainloop would be clobbered by
    // cp.async stages; so keep the value in a register instead of smem:
    float inv_reg = (threadIdx.x < 128) ? s_inv[threadIdx.x] : 0.0f;
    __syncthreads();

    const size_t poff = (size_t)b * SEQ * SEQ + (size_t)row0 * SEQ;
    const size_t voff = (size_t)b * D * SEQ + (size_t)col0 * SEQ;

    float acc[2][8][4] = {};
    gemm_run_f(g_Ef + poff, SEQ, g_Vtf + voff, SEQ, nchunks, acc);

    // republish inv sums to smem (stages dead now; gemm_run_f ended with barrier)
    float* s_inv2 = (float*)dsm;
    if (threadIdx.x < 128) s_inv2[threadIdx.x] = inv_reg;
    __syncthreads();

    store_f32_rowscaled(Out + (size_t)b * SEQ * D, D, row0, col0, acc, s_inv2);
}

// ---------------------------------------------------------------------------
extern "C" void kernel_launch(void* const* d_in, const int* in_sizes, int n_in,
                              void* d_out, int out_size)
{
    const float* X  = (const float*)d_in[0];
    const float* Wq = (const float*)d_in[1];
    const float* Wk = (const float*)d_in[2];
    const float* Wv = (const float*)d_in[3];
    float* Out = (float*)d_out;

    static bool init_done = false;
    if (!init_done) {
        cudaFuncSetAttribute(qkv_mm,    cudaFuncAttributeMaxDynamicSharedMemorySize, DYN_F);
        cudaFuncSetAttribute(scores_mm, cudaFuncAttributeMaxDynamicSharedMemorySize, DYN_F);
        cudaFuncSetAttribute(pv_mm,     cudaFuncAttributeMaxDynamicSharedMemorySize, DYN_F);
        init_done = true;
    }

    __half* xf;
    cudaGetSymbolAddress((void**)&xf, g_Xf);

    cvt_kernel<<<(NTOK * D) / 2048, 256>>>(X, xf, NTOK * D);
    cvtw_kernel<<<dim3((D * D) / 2048, 1, 3), 256>>>(Wq, Wk, Wv);

    qkv_mm<<<dim3(D / 128, NTOK / 128, 3), 256, DYN_F>>>();
    scores_mm<<<dim3(528, BATCH), 256, DYN_F>>>();
    pv_mm<<<dim3(D / 128, (SEQ / 128) * BATCH, 1), 256, DYN_F>>>(Out);
}

// round 17
// speedup vs baseline: 7.0136x; 1.0123x over previous
#include <cuda_runtime.h>
#include <cuda_fp16.h>
#include <math.h>
#include <stdint.h>

#define D     768
#define SEQ   4096
#define BATCH 4
#define NTOK  (BATCH * SEQ)
#define SCALE 0.03608439182435161f  // 1/sqrt(768)

// ---------------------------------------------------------------------------
// Device-global scratch
// ---------------------------------------------------------------------------
__device__ __align__(256) __half g_Xf[NTOK * D];
__device__ __align__(256) __half g_Wf[3 * D * D];
__device__ __align__(256) __half g_Qf[NTOK * D];    // pre-scaled by SCALE
__device__ __align__(256) __half g_Kf[NTOK * D];
__device__ __align__(256) __half g_Vtf[NTOK * D];                 // [b][d][seq]
__device__ __align__(256) __half g_Ef[(size_t)BATCH * SEQ * SEQ]; // exp(S), fp16
__device__ float g_RS[(size_t)BATCH * 64 * SEQ];   // per-64col row partial sums

// fp16 core: 128x64 tiles, stride 72 (144B rows, conflict-free ldmatrix)
#define FSTR     72
#define TILE_F   (128 * FSTR * 2)        // 18432 B
#define STAGE_F  (2 * TILE_F)            // A|B = 36864
#define NSTAGE   3
#define DYN_F    (NSTAGE * STAGE_F)      // 110592 (2 CTAs/SM)

// ---------------------------------------------------------------------------
// PTX helpers
// ---------------------------------------------------------------------------
__device__ __forceinline__ uint32_t smem_u32(const void* p) {
    uint32_t a;
    asm("{ .reg .u64 t; cvta.to.shared.u64 t, %1; cvt.u32.u64 %0, t; }" : "=r"(a) : "l"(p));
    return a;
}
__device__ __forceinline__ void ldsm4(uint32_t r[4], uint32_t addr) {
    asm volatile("ldmatrix.sync.aligned.m8n8.x4.shared.b16 {%0,%1,%2,%3}, [%4];"
                 : "=r"(r[0]), "=r"(r[1]), "=r"(r[2]), "=r"(r[3]) : "r"(addr));
}
__device__ __forceinline__ void mma_f16(float c[4], const uint32_t a[4],
                                        uint32_t b0, uint32_t b1) {
    asm volatile(
        "mma.sync.aligned.m16n8k16.row.col.f32.f16.f16.f32 "
        "{%0,%1,%2,%3}, {%4,%5,%6,%7}, {%8,%9}, {%0,%1,%2,%3};"
        : "+f"(c[0]), "+f"(c[1]), "+f"(c[2]), "+f"(c[3])
        : "r"(a[0]), "r"(a[1]), "r"(a[2]), "r"(a[3]), "r"(b0), "r"(b1));
}
#define CP16(dst, src) asm volatile("cp.async.cg.shared.global [%0], [%1], 16;" :: "r"(dst), "l"(src) : "memory")
#define CP_COMMIT()    asm volatile("cp.async.commit_group;" ::: "memory")
#define CP_WAIT0()     asm volatile("cp.async.wait_group 0;" ::: "memory")
#define CP_WAIT1()     asm volatile("cp.async.wait_group 1;" ::: "memory")

__device__ __forceinline__ unsigned short hfu(__half x) {
    return *reinterpret_cast<unsigned short*>(&x);
}
__device__ __forceinline__ uint32_t pack_h2(float v0, float v1) {
    return (uint32_t)hfu(__float2half_rn(v0)) | ((uint32_t)hfu(__float2half_rn(v1)) << 16);
}

// ===========================================================================
// fp16 single-mma 128x128 GEMM core, 256 threads, K-chunk 64, 3-stage pipe
// ===========================================================================
__device__ __forceinline__ void load_chunk_f(
    uint32_t stage,
    const __half* __restrict__ A, int lda,
    const __half* __restrict__ B, int ldb, int k0)
{
    const int t   = threadIdx.x;
    const int seg = t & 7;        // 16B segment of a 128B row (64 f16)
    const int r0  = t >> 3;       // 0..31
    #pragma unroll
    for (int i = 0; i < 4; i++) {
        const int row = r0 + i * 32;
        const uint32_t so = (uint32_t)(row * FSTR + seg * 8) * 2;
        CP16(stage + so,          A + (size_t)row * lda + k0 + seg * 8);
        CP16(stage + TILE_F + so, B + (size_t)row * ldb + k0 + seg * 8);
    }
}

__device__ __forceinline__ void compute_chunk_f(
    uint32_t stage, const uint32_t offA[2], const uint32_t offB[4],
    float acc[2][8][4])
{
    const uint32_t aT = stage, bT = stage + TILE_F;
    #pragma unroll
    for (int kk = 0; kk < 64; kk += 16) {
        uint32_t af[2][4];
        ldsm4(af[0], aT + offA[0] + kk * 2);
        ldsm4(af[1], aT + offA[1] + kk * 2);
        #pragma unroll
        for (int g = 0; g < 4; g++) {
            uint32_t bf[4];
            ldsm4(bf, bT + offB[g] + kk * 2);
            #pragma unroll
            for (int mt = 0; mt < 2; mt++) {
                #pragma unroll
                for (int nt = 0; nt < 2; nt++)
                    mma_f16(acc[mt][g * 2 + nt], af[mt], bf[nt * 2], bf[nt * 2 + 1]);
            }
        }
    }
}

// final_barrier: true if the caller reuses dynamic smem after the mainloop.
__device__ __forceinline__ void gemm_run_f(
    const __half* __restrict__ A, int lda,
    const __half* __restrict__ B, int ldb,
    int nchunks, bool final_barrier, float acc[2][8][4])
{
    extern __shared__ char dsm[];
    const uint32_t base = smem_u32(dsm);
    const int lane = threadIdx.x & 31;
    const int warp = threadIdx.x >> 5;
    const int wm = warp >> 1, wn = warp & 1;
    const int rowA = ((lane >> 3) & 1) * 8 + (lane & 7);
    const int colA = (lane >> 4) * 8;
    const int rowB = (lane >> 4) * 8 + (lane & 7);
    const int colB = ((lane >> 3) & 1) * 8;

    uint32_t offA[2], offB[4];
    #pragma unroll
    for (int mt = 0; mt < 2; mt++)
        offA[mt] = ((wm * 32 + mt * 16 + rowA) * FSTR + colA) * 2;
    #pragma unroll
    for (int g = 0; g < 4; g++)
        offB[g] = ((wn * 64 + g * 16 + rowB) * FSTR + colB) * 2;

    // Prologue: stages 0 and 1 in flight
    load_chunk_f(base, A, lda, B, ldb, 0);
    CP_COMMIT();
    if (nchunks > 1) {
        load_chunk_f(base + STAGE_F, A, lda, B, ldb, 64);
        CP_COMMIT();
    }

    int s = 0;
    for (int c = 0; c < nchunks; c++) {
        if (c + 1 < nchunks) CP_WAIT1(); else CP_WAIT0();
        __syncthreads();
        if (c + 2 < nchunks) {
            int s2 = s + 2; if (s2 >= NSTAGE) s2 -= NSTAGE;
            load_chunk_f(base + s2 * STAGE_F, A, lda, B, ldb, (c + 2) * 64);
            CP_COMMIT();
        }
        compute_chunk_f(base + s * STAGE_F, offA, offB, acc);
        if (++s == NSTAGE) s = 0;
    }
    if (final_barrier) __syncthreads();
}

// ===========================================================================
// Epilogues (128x128, 8-warp 2x2 layout)
// ===========================================================================
__device__ __forceinline__ void store_f32_rowscaled(
    float* __restrict__ C, size_t ldc, int row0, int col0,
    const float acc[2][8][4], const float* __restrict__ isum)
{
    const int lane = threadIdx.x & 31;
    const int warp = threadIdx.x >> 5;
    const int wm = warp >> 1, wn = warp & 1;
    #pragma unroll
    for (int mt = 0; mt < 2; mt++) {
        const int rt = wm * 32 + mt * 16 + (lane >> 2);
        const int r  = row0 + rt;
        const float i0 = isum[rt];
        const float i1 = isum[rt + 8];
        #pragma unroll
        for (int j = 0; j < 8; j++) {
            const int c = col0 + wn * 64 + j * 8 + (lane & 3) * 2;
            *(float2*)(C + (size_t)r * ldc + c) =
                make_float2(acc[mt][j][0] * i0, acc[mt][j][1] * i0);
            *(float2*)(C + (size_t)(r + 8) * ldc + c) =
                make_float2(acc[mt][j][2] * i1, acc[mt][j][3] * i1);
        }
    }
}

__device__ __forceinline__ void store_f16_t(
    __half* __restrict__ Cf, size_t ldc, int row0, int col0,
    const float acc[2][8][4], float scale)
{
    const int lane = threadIdx.x & 31;
    const int warp = threadIdx.x >> 5;
    const int wm = warp >> 1, wn = warp & 1;
    #pragma unroll
    for (int mt = 0; mt < 2; mt++) {
        const int r = row0 + wm * 32 + mt * 16 + (lane >> 2);
        #pragma unroll
        for (int j = 0; j < 8; j++) {
            const int c = col0 + wn * 64 + j * 8 + (lane & 3) * 2;
            *(uint32_t*)(Cf + (size_t)r * ldc + c) =
                pack_h2(acc[mt][j][0] * scale, acc[mt][j][1] * scale);
            *(uint32_t*)(Cf + (size_t)(r + 8) * ldc + c) =
                pack_h2(acc[mt][j][2] * scale, acc[mt][j][3] * scale);
        }
    }
}

// scores epilogue: E = exp(S) (fp16), causal mask on diagonal tiles, and
// deterministic per-row partial sums (64-col granularity) into g_RS.
__device__ __forceinline__ void store_exp_t(
    __half* __restrict__ Ef, int row0, int col0,
    const float acc[2][8][4], bool diag, int b, int bx)
{
    const int lane = threadIdx.x & 31;
    const int warp = threadIdx.x >> 5;
    const int wm = warp >> 1, wn = warp & 1;
    float* rs_base = g_RS + ((size_t)(b * 64 + bx * 2 + wn)) * SEQ + row0;

    #pragma unroll
    for (int mt = 0; mt < 2; mt++) {
        const int rt = wm * 32 + mt * 16 + (lane >> 2);   // tile-local row
        float rs0 = 0.0f, rs1 = 0.0f;
        #pragma unroll
        for (int j = 0; j < 8; j++) {
            const int ct = wn * 64 + j * 8 + (lane & 3) * 2;  // tile-local col
            float e0 = (!diag || ct     <= rt)     ? __expf(acc[mt][j][0]) : 0.0f;
            float e1 = (!diag || ct + 1 <= rt)     ? __expf(acc[mt][j][1]) : 0.0f;
            float e2 = (!diag || ct     <= rt + 8) ? __expf(acc[mt][j][2]) : 0.0f;
            float e3 = (!diag || ct + 1 <= rt + 8) ? __expf(acc[mt][j][3]) : 0.0f;
            *(uint32_t*)(Ef + (size_t)(row0 + rt) * SEQ + col0 + ct)     = pack_h2(e0, e1);
            *(uint32_t*)(Ef + (size_t)(row0 + rt + 8) * SEQ + col0 + ct) = pack_h2(e2, e3);
            rs0 += e0 + e1;
            rs1 += e2 + e3;
        }
        rs0 += __shfl_xor_sync(0xFFFFFFFF, rs0, 1);
        rs0 += __shfl_xor_sync(0xFFFFFFFF, rs0, 2);
        rs1 += __shfl_xor_sync(0xFFFFFFFF, rs1, 1);
        rs1 += __shfl_xor_sync(0xFFFFFFFF, rs1, 2);
        if ((lane & 3) == 0) {
            rs_base[rt]     = rs0;
            rs_base[rt + 8] = rs1;
        }
    }
}

// Transposed fp16 V store via smem (128x128 tile)
#define VT_STRIDE 136
__device__ __forceinline__ void store_vt_f16(int row0, int col0, const float acc[2][8][4])
{
    extern __shared__ char dsm[];
    unsigned short* sp = (unsigned short*)dsm;
    const int tid  = threadIdx.x;
    const int lane = tid & 31;
    const int warp = tid >> 5;
    const int wm = warp >> 1, wn = warp & 1;

    #pragma unroll
    for (int mt = 0; mt < 2; mt++) {
        const int r = wm * 32 + mt * 16 + (lane >> 2);
        #pragma unroll
        for (int j = 0; j < 8; j++) {
            const int c = wn * 64 + j * 8 + (lane & 3) * 2;
            #pragma unroll
            for (int e = 0; e < 4; e++)
                sp[(r + (e >> 1) * 8) * VT_STRIDE + c + (e & 1)] =
                    hfu(__float2half_rn(acc[mt][j][e]));
        }
    }
    __syncthreads();

    const int b   = row0 >> 12;
    const int rin = row0 & (SEQ - 1);
    const int d   = tid >> 1;
    const int ks  = (tid & 1) * 64;
    __half* dst = g_Vtf + (size_t)b * D * SEQ + (size_t)(col0 + d) * SEQ + rin + ks;
    #pragma unroll
    for (int g = 0; g < 8; g++) {
        uint32_t w[4];
        #pragma unroll
        for (int h = 0; h < 4; h++) {
            uint32_t a0 = sp[(ks + g * 8 + h * 2) * VT_STRIDE + d];
            uint32_t a1 = sp[(ks + g * 8 + h * 2 + 1) * VT_STRIDE + d];
            w[h] = a0 | (a1 << 16);
        }
        *(uint4*)(dst + g * 8) = make_uint4(w[0], w[1], w[2], w[3]);
    }
}

// ===========================================================================
// Kernels
// ===========================================================================
#define XCVT_BLOCKS ((NTOK * D) / 2048)   // 6144
#define WCVT_BLOCKS ((D * D) / 2048)      // 288

// Single conversion launch: X followed by Wq|Wk|Wv.
__global__ void __launch_bounds__(256) cvt_all(const float* __restrict__ X,
                                               const float* __restrict__ wq,
                                               const float* __restrict__ wk,
                                               const float* __restrict__ wv)
{
    const int blk = blockIdx.x;
    const float* src;
    __half* dst;
    int i;
    if (blk < XCVT_BLOCKS) {
        src = X; dst = g_Xf;
        i = (blk * 256 + threadIdx.x) * 8;
    } else {
        const int wb = blk - XCVT_BLOCKS;
        const int z  = wb / WCVT_BLOCKS;           // 0..2
        src = (z == 0) ? wq : (z == 1) ? wk : wv;
        dst = g_Wf + (size_t)z * D * D;
        i = ((wb - z * WCVT_BLOCKS) * 256 + threadIdx.x) * 8;
    }
    float4 v0 = *(const float4*)(src + i);
    float4 v1 = *(const float4*)(src + i + 4);
    *(uint4*)(dst + i) = make_uint4(pack_h2(v0.x, v0.y), pack_h2(v0.z, v0.w),
                                    pack_h2(v1.x, v1.y), pack_h2(v1.z, v1.w));
}

// Q, K, V projection; V (heavier epilogue) scheduled first via z-reversal.
__global__ void __launch_bounds__(256, 2) qkv_mm()
{
    const int z    = 2 - blockIdx.z;               // z=2 (V) dispatches first
    const int row0 = blockIdx.y * 128;
    const int col0 = blockIdx.x * 128;

    float acc[2][8][4] = {};
    gemm_run_f(g_Xf + (size_t)row0 * D, D,
               g_Wf + (size_t)z * D * D + (size_t)col0 * D, D, D / 64,
               z == 2, acc);

    if (z == 0)      store_f16_t(g_Qf, D, row0, col0, acc, SCALE);
    else if (z == 1) store_f16_t(g_Kf, D, row0, col0, acc, 1.0f);
    else             store_vt_f16(row0, col0, acc);
}

// S tile -> exp -> fp16 E + row partial sums
__global__ void __launch_bounds__(256, 2) scores_mm()
{
    const int t = blockIdx.x;
    int by = (int)((sqrtf(8.0f * t + 1.0f) - 1.0f) * 0.5f);
    while ((by + 1) * (by + 2) / 2 <= t) by++;
    while (by * (by + 1) / 2 > t) by--;
    const int bx = t - by * (by + 1) / 2;
    const int b  = blockIdx.y;
    const int row0 = by * 128, col0 = bx * 128;
    const size_t qoff = (size_t)b * SEQ * D;

    float acc[2][8][4] = {};
    gemm_run_f(g_Qf + qoff + (size_t)row0 * D, D,
               g_Kf + qoff + (size_t)col0 * D, D, D / 64, false, acc);
    store_exp_t(g_Ef + (size_t)b * SEQ * SEQ, row0, col0, acc, by == bx, b, bx);
}

// PV: cross-batch heavy-first scheduling; rowsum computed into a register
// before the mainloop (depends only on scores_mm, complete at launch).
__global__ void __launch_bounds__(256, 2) pv_mm(float* __restrict__ Out)
{
    extern __shared__ char dsm[];
    const int idx  = blockIdx.y;
    const int b    = idx & 3;
    const int by   = (SEQ / 128 - 1) - (idx >> 2);   // heavy rows first, all batches
    const int row0 = by * 128;
    const int col0 = blockIdx.x * 128;
    const int nchunks = (by + 1) * 2;                // Klim / 64

    // rowsum -> register (loads overlap the GEMM prologue issued below)
    float inv_reg = 0.0f;
    if (threadIdx.x < 128) {
        const float* rs = g_RS + ((size_t)b * 64) * SEQ + row0 + threadIdx.x;
        float s = 0.0f;
        for (int i = 0; i < nchunks; i++) s += rs[(size_t)i * SEQ];
        inv_reg = 1.0f / s;
    }

    const size_t poff = (size_t)b * SEQ * SEQ + (size_t)row0 * SEQ;
    const size_t voff = (size_t)b * D * SEQ + (size_t)col0 * SEQ;

    float acc[2][8][4] = {};
    gemm_run_f(g_Ef + poff, SEQ, g_Vtf + voff, SEQ, nchunks, true, acc);

    // publish inv sums to smem (stage buffers dead; barrier inside gemm_run_f)
    float* s_inv = (float*)dsm;
    if (threadIdx.x < 128) s_inv[threadIdx.x] = inv_reg;
    __syncthreads();

    store_f32_rowscaled(Out + (size_t)b * SEQ * D, D, row0, col0, acc, s_inv);
}

// ---------------------------------------------------------------------------
extern "C" void kernel_launch(void* const* d_in, const int* in_sizes, int n_in,
                              void* d_out, int out_size)
{
    const float* X  = (const float*)d_in[0];
    const float* Wq = (const float*)d_in[1];
    const float* Wk = (const float*)d_in[2];
    const float* Wv = (const float*)d_in[3];
    float* Out = (float*)d_out;

    static bool init_done = false;
    if (!init_done) {
        cudaFuncSetAttribute(qkv_mm,    cudaFuncAttributeMaxDynamicSharedMemorySize, DYN_F);
        cudaFuncSetAttribute(scores_mm, cudaFuncAttributeMaxDynamicSharedMemorySize, DYN_F);
        cudaFuncSetAttribute(pv_mm,     cudaFuncAttributeMaxDynamicSharedMemorySize, DYN_F);
        init_done = true;
    }

    cvt_all<<<XCVT_BLOCKS + 3 * WCVT_BLOCKS, 256>>>(X, Wq, Wk, Wv);
    qkv_mm<<<dim3(D / 128, NTOK / 128, 3), 256, DYN_F>>>();
    scores_mm<<<dim3(528, BATCH), 256, DYN_F>>>();
    pv_mm<<<dim3(D / 128, (SEQ / 128) * BATCH, 1), 256, DYN_F>>>(Out);
}